// round 15
// baseline (speedup 1.0000x reference)
#include <cuda_runtime.h>
#include <cuda_bf16.h>
#include <math.h>
#include <stdint.h>

#define C 8192
#define D 512
#define BM 128                 // tile rows == tile cols
#define NTILE (C / BM)         // 64
#define BKC 32                 // bf16 K per chunk (two k16-steps)
#define NCH (D / BKC)          // 16 chunks
#define SLAB 8192              // one slab: 128 rows x 32 bf16 (64 B/row)
#define STAGE 32768            // 4 slabs per stage
#define DYN_SMEM 69632         // 2 stages (64 KB); epilogue 128x132 fp32 (66 KB)

// ---------------- scratch (__device__ globals; no allocations allowed) ------
__device__ __nv_bfloat16 g_s0[C * D];    // bf16 split 0 of normalized G
__device__ __nv_bfloat16 g_s1[C * D];    // split 1 (residual)
__device__ float g_pm[NTILE * C];
__device__ float g_pz[NTILE * C];
__device__ float g_pmn[NTILE * C];
__device__ int   g_pimax[NTILE * C];
__device__ int   g_pimin[NTILE * C];
__device__ float g_margin[C];
__device__ int   g_ms[C];
__device__ int   g_ls[C];
__device__ float g_terms[C];

// ---------------- helpers ----------------------------------------------------
__device__ __forceinline__ uint32_t smem_u32(const void* p) {
    uint32_t a;
    asm("{ .reg .u64 t; cvta.to.shared.u64 t, %1; cvt.u32.u64 %0, t; }"
        : "=r"(a) : "l"(p));
    return a;
}
__device__ __forceinline__ void cp16(uint32_t dst, const void* src) {
    asm volatile("cp.async.cg.shared.global [%0], [%1], 16;"
                 :: "r"(dst), "l"(src));
}
#define CP_COMMIT() asm volatile("cp.async.commit_group;" ::: "memory")
#define CP_WAIT(n)  asm volatile("cp.async.wait_group %0;" :: "n"(n) : "memory")
__device__ __forceinline__ void ldsm_x4(uint32_t& r0, uint32_t& r1,
                                        uint32_t& r2, uint32_t& r3,
                                        uint32_t addr) {
    asm volatile("ldmatrix.sync.aligned.m8n8.x4.shared.b16 {%0,%1,%2,%3}, [%4];"
                 : "=r"(r0), "=r"(r1), "=r"(r2), "=r"(r3) : "r"(addr));
}
__device__ __forceinline__ void mma_bf16(float* c,
                                         uint32_t a0, uint32_t a1,
                                         uint32_t a2, uint32_t a3,
                                         uint32_t b0, uint32_t b1) {
    asm volatile(
        "mma.sync.aligned.m16n8k16.row.col.f32.bf16.bf16.f32 "
        "{%0,%1,%2,%3}, {%4,%5,%6,%7}, {%8,%9}, {%0,%1,%2,%3};"
        : "+f"(c[0]), "+f"(c[1]), "+f"(c[2]), "+f"(c[3])
        : "r"(a0), "r"(a1), "r"(a2), "r"(a3), "r"(b0), "r"(b1));
}

// ---------------- 1. row L2-normalize + bf16x2 split ------------------------
__global__ void normalize_split_kernel(const float* __restrict__ g) {
    int r = blockIdx.x;
    int t = threadIdx.x;  // 128 threads, 4 floats each
    float4 v = ((const float4*)(g + (size_t)r * D))[t];
    float ss = v.x * v.x + v.y * v.y + v.z * v.z + v.w * v.w;
#pragma unroll
    for (int o = 16; o; o >>= 1) ss += __shfl_down_sync(0xffffffffu, ss, o);
    __shared__ float sh[4];
    if ((t & 31) == 0) sh[t >> 5] = ss;
    __syncthreads();
    float inv = 1.0f / sqrtf(sh[0] + sh[1] + sh[2] + sh[3]);
    float x[4] = {v.x * inv, v.y * inv, v.z * inv, v.w * inv};
    __nv_bfloat16 b0[4], b1[4];
#pragma unroll
    for (int q = 0; q < 4; q++) {
        b0[q] = __float2bfloat16(x[q]);
        float r1 = x[q] - __bfloat162float(b0[q]);
        b1[q] = __float2bfloat16(r1);
    }
    size_t base = (size_t)r * D + t * 4;
    *(__nv_bfloat162*)(g_s0 + base)     = __nv_bfloat162(b0[0], b0[1]);
    *(__nv_bfloat162*)(g_s0 + base + 2) = __nv_bfloat162(b0[2], b0[3]);
    *(__nv_bfloat162*)(g_s1 + base)     = __nv_bfloat162(b1[0], b1[1]);
    *(__nv_bfloat162*)(g_s1 + base + 2) = __nv_bfloat162(b1[2], b1[3]);
}

// ---------------- 2. mma.sync GEMM tile + row/col stats (symmetric) ---------
// Tile (by,bx), by<=bx. S-tile = 3 bf16 split products (a0b0 + a0b1 + a1b0)
// via m16n8k16 HMMA, cp.async double-buffered chunk pipeline (BKC=32).
// 8 warps: wr = wid>>2 (2 row groups of 64), wc = wid&3 (4 col groups of 32).
__global__ void __launch_bounds__(256, 2) gemm_stats_mma() {
    const int bx = blockIdx.x;
    const int by = blockIdx.y;
    if (by > bx) return;

    extern __shared__ __align__(16) unsigned char dsm[];
    const uint32_t sb = smem_u32(dsm);

    const int tid = threadIdx.x;
    const int wid = tid >> 5, lane = tid & 31;
    const int wr = wid >> 2, wc = wid & 3;
    const int row0 = by * BM, col0 = bx * BM;
    const bool diag = (bx == by);
    const int nslab = diag ? 2 : 4;          // diag: B slabs == A slabs
    const int bbase = diag ? 0 : 2;

    float acc[4][4][4];            // [m-tile][n-tile][frag]
#pragma unroll
    for (int mt = 0; mt < 4; mt++)
#pragma unroll
        for (int nt = 0; nt < 4; nt++)
#pragma unroll
            for (int q = 0; q < 4; q++) acc[mt][nt][q] = 0.0f;

    const __nv_bfloat16* sp[2] = {g_s0, g_s1};

    // stage chunk ch into stage buffer st (cp.async, 64B rows, XOR-4 swizzle)
    auto stage_chunk = [&](int ch, int st) {
        uint32_t stg = sb + st * STAGE;
        for (int s = 0; s < nslab; s++) {
            const __nv_bfloat16* src =
                sp[s & 1] + (size_t)(s < 2 ? row0 : col0) * D + ch * BKC;
#pragma unroll
            for (int q = 0; q < 2; q++) {
                int blk = q * 256 + tid;          // 512 16B blocks per slab
                int row = blk >> 2, cb = blk & 3;
                uint32_t off = row * 64 + ((cb ^ (row & 3)) << 4);
                cp16(stg + s * SLAB + off, src + (size_t)row * D + cb * 8);
            }
        }
        CP_COMMIT();
    };

    // precomputed ldmatrix lane addressing (within-slab offsets)
    const int a_row = (lane & 7) + 8 * ((lane >> 3) & 1);  // + mt*16 + wr*64
    const int a_cbh = lane >> 4;                           // + 2*ks
    const int b_rowp = (lane >> 4) * 8 + (lane & 7);       // + p*16 + wc*32
    const int b_cbh = (lane >> 3) & 1;                     // + 2*ks

    stage_chunk(0, 0);             // prologue

    for (int ch = 0; ch < NCH; ch++) {
        if (ch + 1 < NCH) {        // prefetch next chunk into idle stage
            stage_chunk(ch + 1, (ch + 1) & 1);
            CP_WAIT(1);            // chunk ch arrived (per-thread)
        } else {
            CP_WAIT(0);
        }
        __syncthreads();           // cross-thread visibility of stage ch
        const uint32_t stg = sb + (ch & 1) * STAGE;
        // --- compute: 2 k16-steps x 3 products -----------------------------
#pragma unroll
        for (int ks = 0; ks < 2; ks++) {
#pragma unroll
            for (int s = 0; s < 2; s++) {
                uint32_t a[4][4];
#pragma unroll
                for (int mt = 0; mt < 4; mt++) {
                    int row = wr * 64 + mt * 16 + a_row;
                    int cb = 2 * ks + a_cbh;
                    uint32_t addr = stg + s * SLAB + row * 64 +
                                    ((cb ^ (row & 3)) << 4);
                    ldsm_x4(a[mt][0], a[mt][1], a[mt][2], a[mt][3], addr);
                }
#pragma unroll
                for (int t = 0; t < 2; t++) {
                    if (t >= 2 - s) break;        // pairs: (0,0), (0,1), (1,0)
                    uint32_t b[4][2];
#pragma unroll
                    for (int p = 0; p < 2; p++) {
                        int row = wc * 32 + p * 16 + b_rowp;
                        int cb = 2 * ks + b_cbh;
                        uint32_t addr = stg + (bbase + t) * SLAB + row * 64 +
                                        ((cb ^ (row & 3)) << 4);
                        uint32_t r0, r1, r2, r3;
                        ldsm_x4(r0, r1, r2, r3, addr);
                        b[2 * p][0] = r0;     b[2 * p][1] = r1;
                        b[2 * p + 1][0] = r2; b[2 * p + 1][1] = r3;
                    }
#pragma unroll
                    for (int mt = 0; mt < 4; mt++)
#pragma unroll
                        for (int nt = 0; nt < 4; nt++)
                            mma_bf16(acc[mt][nt], a[mt][0], a[mt][1],
                                     a[mt][2], a[mt][3], b[nt][0], b[nt][1]);
                }
            }
        }
        __syncthreads();           // all done reading stage ch before reuse
    }

    // --- epilogue: dump accumulators to smem transpose buffer ----------------
    float* T = (float*)dsm;        // 128 x 132 fp32 (stages dead now)
    const int g = lane >> 2, tig = lane & 3;
#pragma unroll
    for (int mt = 0; mt < 4; mt++)
#pragma unroll
        for (int nt = 0; nt < 4; nt++) {
            int r0 = wr * 64 + mt * 16 + g;
            int c0 = wc * 32 + nt * 8 + 2 * tig;
            T[r0 * 132 + c0]           = acc[mt][nt][0];
            T[r0 * 132 + c0 + 1]       = acc[mt][nt][1];
            T[(r0 + 8) * 132 + c0]     = acc[mt][nt][2];
            T[(r0 + 8) * 132 + c0 + 1] = acc[mt][nt][3];
        }
    __syncthreads();

    if (tid < 128) {               // row stats: thread = S-row -> slot bx
        const int grow = row0 + tid;
        float m = -1e30f, mn = 1e30f, z = 0.0f;
        int im = 0, imn = 0;
        for (int j = 0; j < 128; j++) {          // ascending col index
            int gcol = col0 + j;
            if (gcol == grow) continue;          // diag (bx==by tiles only)
            float sv = T[tid * 132 + j];
            if (sv > m) { z = z * __expf(m - sv) + 1.0f; m = sv; im = gcol; }
            else        { z += __expf(sv - m); }
            if (sv < mn) { mn = sv; imn = gcol; }
        }
        int idx = bx * C + grow;
        g_pm[idx] = m;  g_pz[idx] = z;  g_pmn[idx] = mn;
        g_pimax[idx] = im;  g_pimin[idx] = imn;
    } else if (!diag) {            // col stats (transpose view) -> slot by
        const int cc = tid - 128;
        const int gcol = col0 + cc;
        float m = -1e30f, mn = 1e30f, z = 0.0f;
        int im = 0, imn = 0;
        for (int rr = 0; rr < 128; rr++) {       // ascending row index
            float sv = T[rr * 132 + cc];
            int gidx = row0 + rr;
            if (sv > m) { z = z * __expf(m - sv) + 1.0f; m = sv; im = gidx; }
            else        { z += __expf(sv - m); }
            if (sv < mn) { mn = sv; imn = gidx; }
        }
        int idx = by * C + gcol;
        g_pm[idx] = m;  g_pz[idx] = z;  g_pmn[idx] = mn;
        g_pimax[idx] = im;  g_pimin[idx] = imn;
    }
}

// ---------------- 3. deterministic per-row merge of NTILE partials ----------
__global__ void combine_kernel() {
    int r = blockIdx.x * blockDim.x + threadIdx.x;
    if (r >= C) return;
    float m = -1e30f, z = 0.0f, mn = 1e30f;
    int im = 0x7fffffff, imn = 0x7fffffff;
    for (int s = 0; s < NTILE; s++) {     // ascending col-tile => tie = min idx
        int idx = s * C + r;
        float m2 = g_pm[idx], z2 = g_pz[idx], mn2 = g_pmn[idx];
        int im2 = g_pimax[idx], imn2 = g_pimin[idx];
        float M = fmaxf(m, m2);
        z = z * __expf(m - M) + z2 * __expf(m2 - M);
        if (m2 > m)       im = im2;
        else if (m2 == m) im = min(im, im2);
        m = M;
        if (mn2 < mn)       { mn = mn2; imn = imn2; }
        else if (mn2 == mn) imn = min(imn, imn2);
    }
    g_margin[r] = (1.0f - __expf(mn - m)) / z;
    g_ms[r] = im;
    g_ls[r] = imn;
}

// ---------------- 4. distances + relu term per row (warp per row) ----------
__global__ void dist_kernel(const float* __restrict__ w) {
    int warp = (blockIdx.x * blockDim.x + threadIdx.x) >> 5;
    int lane = threadIdx.x & 31;
    if (warp >= C) return;
    int r = warp;
    int ms = g_ms[r], ls = g_ls[r];
    const float4* wr = (const float4*)(w + (size_t)r  * D);
    const float4* wm = (const float4*)(w + (size_t)ms * D);
    const float4* wl = (const float4*)(w + (size_t)ls * D);
    float dms = 0.0f, dls = 0.0f;
#pragma unroll
    for (int i = lane; i < D / 4; i += 32) {
        float4 a = wr[i], b = wm[i], c = wl[i];
        float dx;
        dx = a.x - b.x; dms = fmaf(dx, dx, dms);
        dx = a.y - b.y; dms = fmaf(dx, dx, dms);
        dx = a.z - b.z; dms = fmaf(dx, dx, dms);
        dx = a.w - b.w; dms = fmaf(dx, dx, dms);
        dx = a.x - c.x; dls = fmaf(dx, dx, dls);
        dx = a.y - c.y; dls = fmaf(dx, dx, dls);
        dx = a.z - c.z; dls = fmaf(dx, dx, dls);
        dx = a.w - c.w; dls = fmaf(dx, dx, dls);
    }
#pragma unroll
    for (int o = 16; o; o >>= 1) {
        dms += __shfl_down_sync(0xffffffffu, dms, o);
        dls += __shfl_down_sync(0xffffffffu, dls, o);
    }
    if (lane == 0)
        g_terms[r] = fmaxf(0.0f, sqrtf(dms) - sqrtf(dls) + g_margin[r]);
}

// ---------------- 5. deterministic final mean ------------------------------
__global__ void reduce_kernel(float* __restrict__ out) {
    __shared__ float sh[1024];
    int t = threadIdx.x;
    float s = 0.0f;
    for (int i = t; i < C; i += 1024) s += g_terms[i];
    sh[t] = s;
    __syncthreads();
    for (int o = 512; o; o >>= 1) {
        if (t < o) sh[t] += sh[t + o];
        __syncthreads();
    }
    if (t == 0) out[0] = sh[0] / (float)C;
}

// ---------------- launch ----------------------------------------------------
extern "C" void kernel_launch(void* const* d_in, const int* in_sizes, int n_in,
                              void* d_out, int out_size) {
    const float* g = (const float*)d_in[0];  // gt_class_embeddings [8192,512]
    const float* w = (const float*)d_in[1];  // w                   [8192,512]
    float* out = (float*)d_out;

    normalize_split_kernel<<<C, 128>>>(g);
    cudaFuncSetAttribute(gemm_stats_mma,
                         cudaFuncAttributeMaxDynamicSharedMemorySize, DYN_SMEM);
    dim3 grid(NTILE, NTILE);                 // upper triangle does the work
    gemm_stats_mma<<<grid, 256, DYN_SMEM>>>();
    combine_kernel<<<C / 256, 256>>>();
    dist_kernel<<<C / 8, 256>>>(w);          // 8 warps/block, warp per row
    reduce_kernel<<<1, 1024>>>(out);
}

// round 16
// speedup vs baseline: 1.1949x; 1.1949x over previous
#include <cuda_runtime.h>
#include <cuda_bf16.h>
#include <math.h>
#include <stdint.h>

#define C 8192
#define D 512
#define BM 128                 // tile rows == tile cols
#define NTILE (C / BM)         // 64
#define BKC 64                 // bf16 K per chunk
#define NCH (D / BKC)          // 8 chunks
#define SLAB 16384             // one slab: 128 rows x 64 bf16 (128 B/row)
#define DYN_SMEM 69632         // 4 slabs (64 KB); epilogue 128x132 fp32 (66 KB)

// ---------------- scratch (__device__ globals; no allocations allowed) ------
__device__ __nv_bfloat16 g_s0[C * D];    // bf16 split 0 of normalized G
__device__ __nv_bfloat16 g_s1[C * D];    // split 1 (residual)
__device__ float g_pm[NTILE * C];
__device__ float g_pz[NTILE * C];
__device__ float g_pmn[NTILE * C];
__device__ int   g_pimax[NTILE * C];
__device__ int   g_pimin[NTILE * C];
__device__ float g_margin[C];
__device__ int   g_ms[C];
__device__ int   g_ls[C];
__device__ float g_terms[C];

// ---------------- helpers ----------------------------------------------------
__device__ __forceinline__ uint32_t smem_u32(const void* p) {
    uint32_t a;
    asm("{ .reg .u64 t; cvta.to.shared.u64 t, %1; cvt.u32.u64 %0, t; }"
        : "=r"(a) : "l"(p));
    return a;
}
__device__ __forceinline__ void cp16(uint32_t dst, const void* src) {
    asm volatile("cp.async.cg.shared.global [%0], [%1], 16;"
                 :: "r"(dst), "l"(src));
}
#define CP_COMMIT() asm volatile("cp.async.commit_group;" ::: "memory")
#define CP_WAIT0()  asm volatile("cp.async.wait_group 0;" ::: "memory")
__device__ __forceinline__ void ldsm_x4(uint32_t& r0, uint32_t& r1,
                                        uint32_t& r2, uint32_t& r3,
                                        uint32_t addr) {
    asm volatile("ldmatrix.sync.aligned.m8n8.x4.shared.b16 {%0,%1,%2,%3}, [%4];"
                 : "=r"(r0), "=r"(r1), "=r"(r2), "=r"(r3) : "r"(addr));
}
__device__ __forceinline__ void mma_bf16(float* c,
                                         uint32_t a0, uint32_t a1,
                                         uint32_t a2, uint32_t a3,
                                         uint32_t b0, uint32_t b1) {
    asm volatile(
        "mma.sync.aligned.m16n8k16.row.col.f32.bf16.bf16.f32 "
        "{%0,%1,%2,%3}, {%4,%5,%6,%7}, {%8,%9}, {%0,%1,%2,%3};"
        : "+f"(c[0]), "+f"(c[1]), "+f"(c[2]), "+f"(c[3])
        : "r"(a0), "r"(a1), "r"(a2), "r"(a3), "r"(b0), "r"(b1));
}

// ---------------- 1. row L2-normalize + bf16x2 split ------------------------
__global__ void normalize_split_kernel(const float* __restrict__ g) {
    int r = blockIdx.x;
    int t = threadIdx.x;  // 128 threads, 4 floats each
    float4 v = ((const float4*)(g + (size_t)r * D))[t];
    float ss = v.x * v.x + v.y * v.y + v.z * v.z + v.w * v.w;
#pragma unroll
    for (int o = 16; o; o >>= 1) ss += __shfl_down_sync(0xffffffffu, ss, o);
    __shared__ float sh[4];
    if ((t & 31) == 0) sh[t >> 5] = ss;
    __syncthreads();
    float inv = 1.0f / sqrtf(sh[0] + sh[1] + sh[2] + sh[3]);
    float x[4] = {v.x * inv, v.y * inv, v.z * inv, v.w * inv};
    __nv_bfloat16 b0[4], b1[4];
#pragma unroll
    for (int q = 0; q < 4; q++) {
        b0[q] = __float2bfloat16(x[q]);
        float r1 = x[q] - __bfloat162float(b0[q]);
        b1[q] = __float2bfloat16(r1);
    }
    size_t base = (size_t)r * D + t * 4;
    *(__nv_bfloat162*)(g_s0 + base)     = __nv_bfloat162(b0[0], b0[1]);
    *(__nv_bfloat162*)(g_s0 + base + 2) = __nv_bfloat162(b0[2], b0[3]);
    *(__nv_bfloat162*)(g_s1 + base)     = __nv_bfloat162(b1[0], b1[1]);
    *(__nv_bfloat162*)(g_s1 + base + 2) = __nv_bfloat162(b1[2], b1[3]);
}

// ---------------- 2. mma.sync GEMM tile + row/col stats (symmetric) ---------
// Tile (by,bx), by<=bx. S-tile = 3 bf16 split products (a0b0 + a0b1 + a1b0)
// accumulated in fp32 register accumulators via m16n8k16 HMMA. Staging via
// cp.async (same 128B-row XOR-8 swizzle layout, conflict-free LDSM).
// Diagonal tiles stage only the 2 A slabs (B slabs are identical).
// 8 warps: wr = wid>>2 (2 row groups of 64), wc = wid&3 (4 col groups of 32).
__global__ void __launch_bounds__(256, 2) gemm_stats_mma() {
    const int bx = blockIdx.x;
    const int by = blockIdx.y;
    if (by > bx) return;

    extern __shared__ __align__(16) unsigned char dsm[];
    const uint32_t sb = smem_u32(dsm);

    const int tid = threadIdx.x;
    const int wid = tid >> 5, lane = tid & 31;
    const int wr = wid >> 2, wc = wid & 3;
    const int row0 = by * BM, col0 = bx * BM;
    const bool diag = (bx == by);
    const int nslab = diag ? 2 : 4;          // diag: B slabs == A slabs
    const int bbase = diag ? 0 : 2;

    float acc[4][4][4];            // [m-tile][n-tile][frag]
#pragma unroll
    for (int mt = 0; mt < 4; mt++)
#pragma unroll
        for (int nt = 0; nt < 4; nt++)
#pragma unroll
            for (int q = 0; q < 4; q++) acc[mt][nt][q] = 0.0f;

    const __nv_bfloat16* sp[2] = {g_s0, g_s1};

    // precomputed ldmatrix lane addressing (within-slab offsets)
    const int a_row = (lane & 7) + 8 * ((lane >> 3) & 1);  // + mt*16 + wr*64
    const int a_cbh = lane >> 4;                           // + 2*ks
    const int b_rowp = (lane >> 4) * 8 + (lane & 7);       // + p*16 + wc*32
    const int b_cbh = (lane >> 3) & 1;                     // + 2*ks

    for (int ch = 0; ch < NCH; ch++) {
        __syncthreads();           // prev compute done before overwrite
        // --- stage slabs via cp.async (issue-only; one wait per chunk) -----
        for (int s = 0; s < nslab; s++) {
            const __nv_bfloat16* src =
                sp[s & 1] + (size_t)(s < 2 ? row0 : col0) * D + ch * BKC;
#pragma unroll
            for (int q = 0; q < 4; q++) {
                int blk = q * 256 + tid;          // 1024 16B blocks per slab
                int row = blk >> 3, cb = blk & 7;
                uint32_t off = row * 128 + ((cb ^ (row & 7)) << 4);
                cp16(sb + s * SLAB + off, src + (size_t)row * D + cb * 8);
            }
        }
        CP_COMMIT();
        CP_WAIT0();
        __syncthreads();
        // --- compute: 4 k16-steps x 3 products -----------------------------
#pragma unroll
        for (int ks = 0; ks < 4; ks++) {
#pragma unroll
            for (int s = 0; s < 2; s++) {
                uint32_t a[4][4];
#pragma unroll
                for (int mt = 0; mt < 4; mt++) {
                    int row = wr * 64 + mt * 16 + a_row;
                    int cb = 2 * ks + a_cbh;
                    uint32_t addr = sb + s * SLAB + row * 128 +
                                    ((cb ^ (row & 7)) << 4);
                    ldsm_x4(a[mt][0], a[mt][1], a[mt][2], a[mt][3], addr);
                }
#pragma unroll
                for (int t = 0; t < 2; t++) {
                    if (t >= 2 - s) break;        // pairs: (0,0), (0,1), (1,0)
                    uint32_t b[4][2];
#pragma unroll
                    for (int p = 0; p < 2; p++) {
                        int row = wc * 32 + p * 16 + b_rowp;
                        int cb = 2 * ks + b_cbh;
                        uint32_t addr = sb + (bbase + t) * SLAB + row * 128 +
                                        ((cb ^ (row & 7)) << 4);
                        uint32_t r0, r1, r2, r3;
                        ldsm_x4(r0, r1, r2, r3, addr);
                        b[2 * p][0] = r0;     b[2 * p][1] = r1;
                        b[2 * p + 1][0] = r2; b[2 * p + 1][1] = r3;
                    }
#pragma unroll
                    for (int mt = 0; mt < 4; mt++)
#pragma unroll
                        for (int nt = 0; nt < 4; nt++)
                            mma_bf16(acc[mt][nt], a[mt][0], a[mt][1],
                                     a[mt][2], a[mt][3], b[nt][0], b[nt][1]);
                }
            }
        }
    }

    // --- epilogue: dump accumulators to smem transpose buffer ----------------
    __syncthreads();               // all warps done reading slabs
    float* T = (float*)dsm;        // 128 x 132 fp32
    const int g = lane >> 2, tig = lane & 3;
#pragma unroll
    for (int mt = 0; mt < 4; mt++)
#pragma unroll
        for (int nt = 0; nt < 4; nt++) {
            int r0 = wr * 64 + mt * 16 + g;
            int c0 = wc * 32 + nt * 8 + 2 * tig;
            T[r0 * 132 + c0]           = acc[mt][nt][0];
            T[r0 * 132 + c0 + 1]       = acc[mt][nt][1];
            T[(r0 + 8) * 132 + c0]     = acc[mt][nt][2];
            T[(r0 + 8) * 132 + c0 + 1] = acc[mt][nt][3];
        }
    __syncthreads();

    if (tid < 128) {               // row stats: thread = S-row -> slot bx
        const int grow = row0 + tid;
        float m = -1e30f, mn = 1e30f, z = 0.0f;
        int im = 0, imn = 0;
        for (int j = 0; j < 128; j++) {          // ascending col index
            int gcol = col0 + j;
            if (gcol == grow) continue;          // diag (bx==by tiles only)
            float sv = T[tid * 132 + j];
            if (sv > m) { z = z * __expf(m - sv) + 1.0f; m = sv; im = gcol; }
            else        { z += __expf(sv - m); }
            if (sv < mn) { mn = sv; imn = gcol; }
        }
        int idx = bx * C + grow;
        g_pm[idx] = m;  g_pz[idx] = z;  g_pmn[idx] = mn;
        g_pimax[idx] = im;  g_pimin[idx] = imn;
    } else if (!diag) {            // col stats (transpose view) -> slot by
        const int cc = tid - 128;
        const int gcol = col0 + cc;
        float m = -1e30f, mn = 1e30f, z = 0.0f;
        int im = 0, imn = 0;
        for (int rr = 0; rr < 128; rr++) {       // ascending row index
            float sv = T[rr * 132 + cc];
            int gidx = row0 + rr;
            if (sv > m) { z = z * __expf(m - sv) + 1.0f; m = sv; im = gidx; }
            else        { z += __expf(sv - m); }
            if (sv < mn) { mn = sv; imn = gidx; }
        }
        int idx = by * C + gcol;
        g_pm[idx] = m;  g_pz[idx] = z;  g_pmn[idx] = mn;
        g_pimax[idx] = im;  g_pimin[idx] = imn;
    }
}

// ---------------- 3. deterministic per-row merge of NTILE partials ----------
__global__ void combine_kernel() {
    int r = blockIdx.x * blockDim.x + threadIdx.x;
    if (r >= C) return;
    float m = -1e30f, z = 0.0f, mn = 1e30f;
    int im = 0x7fffffff, imn = 0x7fffffff;
    for (int s = 0; s < NTILE; s++) {     // ascending col-tile => tie = min idx
        int idx = s * C + r;
        float m2 = g_pm[idx], z2 = g_pz[idx], mn2 = g_pmn[idx];
        int im2 = g_pimax[idx], imn2 = g_pimin[idx];
        float M = fmaxf(m, m2);
        z = z * __expf(m - M) + z2 * __expf(m2 - M);
        if (m2 > m)       im = im2;
        else if (m2 == m) im = min(im, im2);
        m = M;
        if (mn2 < mn)       { mn = mn2; imn = imn2; }
        else if (mn2 == mn) imn = min(imn, imn2);
    }
    g_margin[r] = (1.0f - __expf(mn - m)) / z;
    g_ms[r] = im;
    g_ls[r] = imn;
}

// ---------------- 4. distances + relu term per row (warp per row) ----------
__global__ void dist_kernel(const float* __restrict__ w) {
    int warp = (blockIdx.x * blockDim.x + threadIdx.x) >> 5;
    int lane = threadIdx.x & 31;
    if (warp >= C) return;
    int r = warp;
    int ms = g_ms[r], ls = g_ls[r];
    const float4* wr = (const float4*)(w + (size_t)r  * D);
    const float4* wm = (const float4*)(w + (size_t)ms * D);
    const float4* wl = (const float4*)(w + (size_t)ls * D);
    float dms = 0.0f, dls = 0.0f;
#pragma unroll
    for (int i = lane; i < D / 4; i += 32) {
        float4 a = wr[i], b = wm[i], c = wl[i];
        float dx;
        dx = a.x - b.x; dms = fmaf(dx, dx, dms);
        dx = a.y - b.y; dms = fmaf(dx, dx, dms);
        dx = a.z - b.z; dms = fmaf(dx, dx, dms);
        dx = a.w - b.w; dms = fmaf(dx, dx, dms);
        dx = a.x - c.x; dls = fmaf(dx, dx, dls);
        dx = a.y - c.y; dls = fmaf(dx, dx, dls);
        dx = a.z - c.z; dls = fmaf(dx, dx, dls);
        dx = a.w - c.w; dls = fmaf(dx, dx, dls);
    }
#pragma unroll
    for (int o = 16; o; o >>= 1) {
        dms += __shfl_down_sync(0xffffffffu, dms, o);
        dls += __shfl_down_sync(0xffffffffu, dls, o);
    }
    if (lane == 0)
        g_terms[r] = fmaxf(0.0f, sqrtf(dms) - sqrtf(dls) + g_margin[r]);
}

// ---------------- 5. deterministic final mean ------------------------------
__global__ void reduce_kernel(float* __restrict__ out) {
    __shared__ float sh[1024];
    int t = threadIdx.x;
    float s = 0.0f;
    for (int i = t; i < C; i += 1024) s += g_terms[i];
    sh[t] = s;
    __syncthreads();
    for (int o = 512; o; o >>= 1) {
        if (t < o) sh[t] += sh[t + o];
        __syncthreads();
    }
    if (t == 0) out[0] = sh[0] / (float)C;
}

// ---------------- launch ----------------------------------------------------
extern "C" void kernel_launch(void* const* d_in, const int* in_sizes, int n_in,
                              void* d_out, int out_size) {
    const float* g = (const float*)d_in[0];  // gt_class_embeddings [8192,512]
    const float* w = (const float*)d_in[1];  // w                   [8192,512]
    float* out = (float*)d_out;

    normalize_split_kernel<<<C, 128>>>(g);
    cudaFuncSetAttribute(gemm_stats_mma,
                         cudaFuncAttributeMaxDynamicSharedMemorySize, DYN_SMEM);
    dim3 grid(NTILE, NTILE);                 // upper triangle does the work
    gemm_stats_mma<<<grid, 256, DYN_SMEM>>>();
    combine_kernel<<<C / 256, 256>>>();
    dist_kernel<<<C / 8, 256>>>(w);          // 8 warps/block, warp per row
    reduce_kernel<<<1, 1024>>>(out);
}